// round 4
// baseline (speedup 1.0000x reference)
#include <cuda_runtime.h>

// Problem constants
#define BB 2
#define SS 2048
#define DD 1024
#define HH 16
#define HD 64
#define MM (BB * SS)   // 4096 rows

// Scratch (device globals: allocation-free per harness rules)
__device__ float g_q[BB * HH * SS * HD];     // [B,H,S,hd] 16 MB
__device__ float g_k[BB * HH * SS * HD];
__device__ float g_v[BB * HH * SS * HD];
__device__ float g_attn[MM * DD];            // [B,S,D] 16 MB

// ---------------------------------------------------------------------------
// Generic NT GEMM: C[M,N] = A[M,K] @ W[N,K]^T, K = 1024, tiles 128x128x16.
// MODE 0: N=3072, scatter epilogue into g_q/g_k/g_v ([B,H,S,hd] layout)
// MODE 1: N=1024, plain row-major epilogue into `out`
// ---------------------------------------------------------------------------
template <int MODE>
__global__ void __launch_bounds__(256) gemm_nt_kernel(
    const float* __restrict__ A, const float* __restrict__ W,
    float* __restrict__ out)
{
    constexpr int BM = 128, BN = 128, BK = 16;
    constexpr int K = 1024;

    __shared__ float As[BK][BM];
    __shared__ float Bs[BK][BN];

    const int tid = threadIdx.x;
    const int tx = tid & 15;        // 0..15 -> 8 output cols
    const int ty = tid >> 4;        // 0..15 -> 8 output rows
    const int m0 = blockIdx.y * BM;
    const int n0 = blockIdx.x * BN;

    float acc[8][8];
#pragma unroll
    for (int i = 0; i < 8; i++)
#pragma unroll
        for (int j = 0; j < 8; j++) acc[i][j] = 0.f;

    for (int k0 = 0; k0 < K; k0 += BK) {
        // Load A and W tiles (each 128 rows x 16 k), store k-major in smem.
#pragma unroll
        for (int p = 0; p < 2; p++) {
            int v   = tid + p * 256;       // 0..511
            int row = v >> 2;              // 0..127
            int kc  = (v & 3) * 4;         // 0,4,8,12
            float4 a = *(const float4*)&A[(size_t)(m0 + row) * K + k0 + kc];
            As[kc + 0][row] = a.x; As[kc + 1][row] = a.y;
            As[kc + 2][row] = a.z; As[kc + 3][row] = a.w;
            float4 b = *(const float4*)&W[(size_t)(n0 + row) * K + k0 + kc];
            Bs[kc + 0][row] = b.x; Bs[kc + 1][row] = b.y;
            Bs[kc + 2][row] = b.z; Bs[kc + 3][row] = b.w;
        }
        __syncthreads();

#pragma unroll
        for (int k = 0; k < BK; k++) {
            float4 a0 = *(const float4*)&As[k][ty * 8];
            float4 a1 = *(const float4*)&As[k][ty * 8 + 4];
            float4 b0 = *(const float4*)&Bs[k][tx * 8];
            float4 b1 = *(const float4*)&Bs[k][tx * 8 + 4];
            float av[8] = {a0.x, a0.y, a0.z, a0.w, a1.x, a1.y, a1.z, a1.w};
            float bv[8] = {b0.x, b0.y, b0.z, b0.w, b1.x, b1.y, b1.z, b1.w};
#pragma unroll
            for (int i = 0; i < 8; i++)
#pragma unroll
                for (int j = 0; j < 8; j++)
                    acc[i][j] = fmaf(av[i], bv[j], acc[i][j]);
        }
        __syncthreads();
    }

    if (MODE == 0) {
        // Scatter into q/k/v: n -> (which, h, d), m -> (b, s)
#pragma unroll
        for (int i = 0; i < 8; i++) {
            int m = m0 + ty * 8 + i;
            int b = m >> 11;          // /2048
            int s = m & 2047;
#pragma unroll
            for (int j = 0; j < 8; j++) {
                int n = n0 + tx * 8 + j;
                int which = n >> 10;
                int r = n & 1023;
                int h = r >> 6;
                int d = r & 63;
                size_t idx = (((size_t)b * HH + h) * SS + s) * HD + d;
                float* dst = (which == 0) ? g_q : (which == 1) ? g_k : g_v;
                dst[idx] = acc[i][j];
            }
        }
    } else {
#pragma unroll
        for (int i = 0; i < 8; i++) {
            int m = m0 + ty * 8 + i;
            float4 c0 = {acc[i][0], acc[i][1], acc[i][2], acc[i][3]};
            float4 c1 = {acc[i][4], acc[i][5], acc[i][6], acc[i][7]};
            *(float4*)&out[(size_t)m * DD + n0 + tx * 8]     = c0;
            *(float4*)&out[(size_t)m * DD + n0 + tx * 8 + 4] = c1;
        }
    }
}

// ---------------------------------------------------------------------------
// Flash-style attention: per CTA one (b, h, 64-row q tile); iterate 32-key
// blocks with online softmax. Static smem = 44 KB (< 48 KB, no attr calls).
// ---------------------------------------------------------------------------
__global__ void __launch_bounds__(256) attn_kernel()
{
    __shared__ float Qs[64][68];
    __shared__ float Ks[32][68];
    __shared__ float Vs[32][68];
    __shared__ float Ps[64][36];

    const int qt = blockIdx.x;   // 0..31 (q tile)
    const int h  = blockIdx.y;
    const int b  = blockIdx.z;
    const int tid = threadIdx.x;
    const int tx = tid & 15;     // 16 col-threads
    const int ty = tid >> 4;     // 16 row-threads (4 rows each)

    const size_t head_base = ((size_t)b * HH + h) * SS * HD;
    const float* qbase = g_q + head_base + (size_t)qt * 64 * HD;
    const float* kbase = g_k + head_base;
    const float* vbase = g_v + head_base;

    // Load and pre-scale Q tile (scale = 1/sqrt(64) = 0.125)
#pragma unroll
    for (int p = 0; p < 4; p++) {
        int v   = tid + p * 256;     // 0..1023
        int row = v >> 4;            // 0..63
        int c4  = (v & 15) * 4;      // 0..60
        float4 q = *(const float4*)&qbase[(size_t)row * HD + c4];
        q.x *= 0.125f; q.y *= 0.125f; q.z *= 0.125f; q.w *= 0.125f;
        *(float4*)&Qs[row][c4] = q;
    }

    float mrow[4], lrow[4], o[4][4];
#pragma unroll
    for (int i = 0; i < 4; i++) {
        mrow[i] = -INFINITY; lrow[i] = 0.f;
#pragma unroll
        for (int j = 0; j < 4; j++) o[i][j] = 0.f;
    }

    for (int kb = 0; kb < SS / 32; kb++) {
        __syncthreads();   // protect Ks/Vs/Ps from previous iteration readers
        // Load K,V tiles 32x64 (512 float4 each; 2 per thread per tile)
#pragma unroll
        for (int p = 0; p < 2; p++) {
            int v   = tid + p * 256;   // 0..511
            int row = v >> 4;          // 0..31
            int c4  = (v & 15) * 4;
            *(float4*)&Ks[row][c4] =
                *(const float4*)&kbase[((size_t)kb * 32 + row) * HD + c4];
            *(float4*)&Vs[row][c4] =
                *(const float4*)&vbase[((size_t)kb * 32 + row) * HD + c4];
        }
        __syncthreads();

        // Scores: s2[i][j] for rows ty*4+i, cols tx*2+j
        float s2[4][2] = {{0.f,0.f},{0.f,0.f},{0.f,0.f},{0.f,0.f}};
#pragma unroll
        for (int d4 = 0; d4 < 16; d4++) {
            float4 qv[4], kv[2];
#pragma unroll
            for (int i = 0; i < 4; i++) qv[i] = *(const float4*)&Qs[ty * 4 + i][d4 * 4];
#pragma unroll
            for (int j = 0; j < 2; j++) kv[j] = *(const float4*)&Ks[tx * 2 + j][d4 * 4];
#pragma unroll
            for (int i = 0; i < 4; i++)
#pragma unroll
                for (int j = 0; j < 2; j++) {
                    s2[i][j] = fmaf(qv[i].x, kv[j].x, s2[i][j]);
                    s2[i][j] = fmaf(qv[i].y, kv[j].y, s2[i][j]);
                    s2[i][j] = fmaf(qv[i].z, kv[j].z, s2[i][j]);
                    s2[i][j] = fmaf(qv[i].w, kv[j].w, s2[i][j]);
                }
        }

        // Online softmax per row (row spread across a 16-lane half-warp)
#pragma unroll
        for (int i = 0; i < 4; i++) {
            float mx = fmaxf(s2[i][0], s2[i][1]);
#pragma unroll
            for (int off = 1; off < 16; off <<= 1)
                mx = fmaxf(mx, __shfl_xor_sync(0xffffffffu, mx, off));
            float mnew  = fmaxf(mrow[i], mx);
            float alpha = __expf(mrow[i] - mnew);
            float p0 = __expf(s2[i][0] - mnew);
            float p1 = __expf(s2[i][1] - mnew);
            float rs = p0 + p1;
#pragma unroll
            for (int off = 1; off < 16; off <<= 1)
                rs += __shfl_xor_sync(0xffffffffu, rs, off);
            lrow[i] = lrow[i] * alpha + rs;
            mrow[i] = mnew;
#pragma unroll
            for (int j = 0; j < 4; j++) o[i][j] *= alpha;
            Ps[ty * 4 + i][tx * 2 + 0] = p0;
            Ps[ty * 4 + i][tx * 2 + 1] = p1;
        }
        __syncthreads();

        // O += P @ V  (o cols = tx*4 .. tx*4+3)
#pragma unroll
        for (int c = 0; c < 32; c++) {
            float4 v4 = *(const float4*)&Vs[c][tx * 4];
            float pc[4];
#pragma unroll
            for (int i = 0; i < 4; i++) pc[i] = Ps[ty * 4 + i][c];
#pragma unroll
            for (int i = 0; i < 4; i++) {
                o[i][0] = fmaf(pc[i], v4.x, o[i][0]);
                o[i][1] = fmaf(pc[i], v4.y, o[i][1]);
                o[i][2] = fmaf(pc[i], v4.z, o[i][2]);
                o[i][3] = fmaf(pc[i], v4.w, o[i][3]);
            }
        }
    }

    // Finalize: divide by l, write to g_attn [B,S,D] with D index h*64+col
#pragma unroll
    for (int i = 0; i < 4; i++) {
        float inv = 1.f / lrow[i];
        int srow = qt * 64 + ty * 4 + i;
        float4 r = {o[i][0] * inv, o[i][1] * inv, o[i][2] * inv, o[i][3] * inv};
        *(float4*)&g_attn[((size_t)b * SS + srow) * DD + h * HD + tx * 4] = r;
    }
}

// ---------------------------------------------------------------------------
extern "C" void kernel_launch(void* const* d_in, const int* in_sizes, int n_in,
                              void* d_out, int out_size)
{
    const float* x     = (const float*)d_in[0];   // [2,2048,1024]
    const float* w_qkv = (const float*)d_in[1];   // [3072,1024]
    const float* w_out = (const float*)d_in[2];   // [1024,1024]
    float* out = (float*)d_out;                   // [2,2048,1024]

    float* g_attn_ptr;
    cudaGetSymbolAddress((void**)&g_attn_ptr, g_attn);

    // 1) QKV projection + head scatter
    dim3 g1(3072 / 128, MM / 128);
    gemm_nt_kernel<0><<<g1, 256>>>(x, w_qkv, nullptr);

    // 2) Attention
    dim3 g2(SS / 64, HH, BB);
    attn_kernel<<<g2, 256>>>();

    // 3) Output projection
    dim3 g3(DD / 128, MM / 128);
    gemm_nt_kernel<1><<<g3, 256>>>(g_attn_ptr, w_out, out);
}

// round 5
// speedup vs baseline: 2.0614x; 2.0614x over previous
#include <cuda_runtime.h>
#include <math.h>

// Problem constants
#define BB 2
#define SS 2048
#define DD 1024
#define HH 16
#define HD 64
#define MM (BB * SS)   // 4096 rows

// Scratch (device globals: allocation-free per harness rules)
__device__ float g_q[BB * HH * SS * HD];     // [B,H,S,hd]
__device__ float g_k[BB * HH * SS * HD];
__device__ float g_v[BB * HH * SS * HD];
__device__ float g_attn[MM * DD];            // [B,S,D]

// ---------------------------------------------------------------------------
// tf32 helpers
// ---------------------------------------------------------------------------
__device__ __forceinline__ unsigned f2t(float x) {
    unsigned r;
    asm("cvt.rna.tf32.f32 %0, %1;" : "=r"(r) : "f"(x));
    return r;
}

__device__ __forceinline__ void mma8(float c[4], const unsigned a[4],
                                     const unsigned b[2]) {
    asm volatile(
        "mma.sync.aligned.m16n8k8.row.col.f32.tf32.tf32.f32 "
        "{%0,%1,%2,%3}, {%4,%5,%6,%7}, {%8,%9}, {%0,%1,%2,%3};"
        : "+f"(c[0]), "+f"(c[1]), "+f"(c[2]), "+f"(c[3])
        : "r"(a[0]), "r"(a[1]), "r"(a[2]), "r"(a[3]), "r"(b[0]), "r"(b[1]));
}

// ---------------------------------------------------------------------------
// tf32x3 NT GEMM: C[M,N] = A[M,K] @ W[N,K]^T, K=1024. BM=BN=128, BK=8,
// double-buffered smem (48KB exactly). 8 warps: 2(m) x 4(n), warp tile 64x32.
// MODE 0: scatter epilogue into g_q/g_k/g_v.   MODE 1: row-major into out.
// ---------------------------------------------------------------------------
template <int MODE>
__global__ void __launch_bounds__(256) gemm_tc(
    const float* __restrict__ A, const float* __restrict__ W,
    float* __restrict__ out)
{
    constexpr int K = 1024, BK = 8, PITCH = 12;
    __shared__ unsigned Ah[2][128 * PITCH], Al[2][128 * PITCH];
    __shared__ unsigned Bh[2][128 * PITCH], Bl[2][128 * PITCH];

    const int tid  = threadIdx.x;
    const int lane = tid & 31, warp = tid >> 5;
    const int wm = warp >> 2, wn = warp & 3;   // 2 x 4 warp grid
    const int m0 = blockIdx.y * 128, n0 = blockIdx.x * 128;
    const int g = lane >> 2, tg = lane & 3;

    const int lrow = tid >> 1;          // 0..127
    const int lc4  = (tid & 1) * 4;     // 0 or 4
    const float* Aptr = A + (size_t)(m0 + lrow) * K + lc4;
    const float* Wptr = W + (size_t)(n0 + lrow) * K + lc4;

    float acc[4][4][4];
#pragma unroll
    for (int i = 0; i < 4; i++)
#pragma unroll
        for (int j = 0; j < 4; j++)
#pragma unroll
            for (int c = 0; c < 4; c++) acc[i][j][c] = 0.f;

    auto stage = [&](int buf, float4 a, float4 w) {
        unsigned hi[4], lo[4];
        float av[4] = {a.x, a.y, a.z, a.w};
#pragma unroll
        for (int i = 0; i < 4; i++) {
            hi[i] = f2t(av[i]);
            lo[i] = f2t(av[i] - __uint_as_float(hi[i]));
        }
        *(uint4*)&Ah[buf][lrow * PITCH + lc4] = make_uint4(hi[0], hi[1], hi[2], hi[3]);
        *(uint4*)&Al[buf][lrow * PITCH + lc4] = make_uint4(lo[0], lo[1], lo[2], lo[3]);
        float wv[4] = {w.x, w.y, w.z, w.w};
#pragma unroll
        for (int i = 0; i < 4; i++) {
            hi[i] = f2t(wv[i]);
            lo[i] = f2t(wv[i] - __uint_as_float(hi[i]));
        }
        *(uint4*)&Bh[buf][lrow * PITCH + lc4] = make_uint4(hi[0], hi[1], hi[2], hi[3]);
        *(uint4*)&Bl[buf][lrow * PITCH + lc4] = make_uint4(lo[0], lo[1], lo[2], lo[3]);
    };

    auto compute = [&](int buf) {
        unsigned bh[4][2], bl[4][2];
#pragma unroll
        for (int nt = 0; nt < 4; nt++) {
            int r = (wn * 32 + nt * 8 + g) * PITCH + tg;
            bh[nt][0] = Bh[buf][r]; bh[nt][1] = Bh[buf][r + 4];
            bl[nt][0] = Bl[buf][r]; bl[nt][1] = Bl[buf][r + 4];
        }
#pragma unroll
        for (int mt = 0; mt < 4; mt++) {
            int r0 = (wm * 64 + mt * 16 + g) * PITCH + tg;
            int r1 = r0 + 8 * PITCH;
            unsigned ah[4] = {Ah[buf][r0], Ah[buf][r1], Ah[buf][r0 + 4], Ah[buf][r1 + 4]};
            unsigned al[4] = {Al[buf][r0], Al[buf][r1], Al[buf][r0 + 4], Al[buf][r1 + 4]};
#pragma unroll
            for (int nt = 0; nt < 4; nt++) {
                mma8(acc[mt][nt], al, bh[nt]);   // small terms first
                mma8(acc[mt][nt], ah, bl[nt]);
                mma8(acc[mt][nt], ah, bh[nt]);
            }
        }
    };

    {
        float4 a = *(const float4*)Aptr;
        float4 w = *(const float4*)Wptr;
        stage(0, a, w);
    }
    __syncthreads();
    int buf = 0;
    for (int k0 = BK; k0 < K; k0 += BK) {
        float4 a = *(const float4*)(Aptr + k0);
        float4 w = *(const float4*)(Wptr + k0);
        compute(buf);
        stage(buf ^ 1, a, w);
        __syncthreads();
        buf ^= 1;
    }
    compute(buf);

    // Epilogue
    if (MODE == 0) {
#pragma unroll
        for (int mt = 0; mt < 4; mt++) {
#pragma unroll
            for (int rr = 0; rr < 2; rr++) {
                int m = m0 + wm * 64 + mt * 16 + g + rr * 8;
                int b = m >> 11, s = m & 2047;
#pragma unroll
                for (int nt = 0; nt < 4; nt++) {
                    int n = n0 + wn * 32 + nt * 8 + 2 * tg;
                    int which = n >> 10;
                    int rem = n & 1023, h = rem >> 6, d = rem & 63;
                    float* dst = (which == 0) ? g_q : (which == 1) ? g_k : g_v;
                    float2 val = {acc[mt][nt][rr * 2], acc[mt][nt][rr * 2 + 1]};
                    *(float2*)&dst[(((size_t)b * HH + h) * SS + s) * HD + d] = val;
                }
            }
        }
    } else {
#pragma unroll
        for (int mt = 0; mt < 4; mt++) {
#pragma unroll
            for (int rr = 0; rr < 2; rr++) {
                int m = m0 + wm * 64 + mt * 16 + g + rr * 8;
#pragma unroll
                for (int nt = 0; nt < 4; nt++) {
                    int n = n0 + wn * 32 + nt * 8 + 2 * tg;
                    float2 val = {acc[mt][nt][rr * 2], acc[mt][nt][rr * 2 + 1]};
                    *(float2*)&out[(size_t)m * DD + n] = val;
                }
            }
        }
    }
}

// ---------------------------------------------------------------------------
// tf32 flash attention: BQ=128 rows per CTA (8 warps x 16 rows), 64-key
// blocks, online softmax fully warp-local. Dynamic smem 70656 B.
//   Ks[64][68] (keys x d), Vs[64][72] (keys x d), Ps[128][68] (q x keys)
// ---------------------------------------------------------------------------
#define KS_PITCH 68
#define VS_PITCH 72
#define PS_PITCH 68
#define SMEM_ATTN ((64 * KS_PITCH + 64 * VS_PITCH + 128 * PS_PITCH) * 4)

__global__ void __launch_bounds__(256) attn_tc()
{
    extern __shared__ unsigned sm[];
    unsigned* Ks = sm;                       // 64*68
    unsigned* Vs = Ks + 64 * KS_PITCH;       // 64*72
    unsigned* Ps = Vs + 64 * VS_PITCH;       // 128*68

    const int qt = blockIdx.x, h = blockIdx.y, b = blockIdx.z;
    const int tid = threadIdx.x, lane = tid & 31, warp = tid >> 5;
    const int g = lane >> 2, tg = lane & 3;

    const size_t hb = ((size_t)b * HH + h) * SS * HD;
    const float* qp = g_q + hb + (size_t)qt * 128 * HD;
    const float* kp = g_k + hb;
    const float* vp = g_v + hb;

    // Q fragments in registers, pre-scaled by 1/sqrt(hd)=0.125
    unsigned qa[8][4];
    {
        int r0 = warp * 16 + g, r1 = r0 + 8;
#pragma unroll
        for (int kk = 0; kk < 8; kk++) {
            int c0 = kk * 8 + tg, c1 = c0 + 4;
            qa[kk][0] = f2t(0.125f * qp[(size_t)r0 * HD + c0]);
            qa[kk][1] = f2t(0.125f * qp[(size_t)r1 * HD + c0]);
            qa[kk][2] = f2t(0.125f * qp[(size_t)r0 * HD + c1]);
            qa[kk][3] = f2t(0.125f * qp[(size_t)r1 * HD + c1]);
        }
    }

    float o[8][4];
#pragma unroll
    for (int i = 0; i < 8; i++)
#pragma unroll
        for (int j = 0; j < 4; j++) o[i][j] = 0.f;
    float mx[2] = {-INFINITY, -INFINITY};
    float l[2] = {0.f, 0.f};

    for (int kb = 0; kb < SS / 64; kb++) {
        // Load K,V 64x64 tiles (cvt to tf32)
#pragma unroll
        for (int p = 0; p < 4; p++) {
            int v = tid + p * 256;            // 0..1023
            int row = v >> 4, c4 = (v & 15) * 4;
            float4 kv = *(const float4*)&kp[((size_t)kb * 64 + row) * HD + c4];
            *(uint4*)&Ks[row * KS_PITCH + c4] =
                make_uint4(f2t(kv.x), f2t(kv.y), f2t(kv.z), f2t(kv.w));
            float4 vv = *(const float4*)&vp[((size_t)kb * 64 + row) * HD + c4];
            *(uint4*)&Vs[row * VS_PITCH + c4] =
                make_uint4(f2t(vv.x), f2t(vv.y), f2t(vv.z), f2t(vv.w));
        }
        __syncthreads();

        // S = Q @ K^T  (warp: 16 rows x 64 keys, 8 n-tiles)
        float s[8][4];
#pragma unroll
        for (int nt = 0; nt < 8; nt++) {
            s[nt][0] = s[nt][1] = s[nt][2] = s[nt][3] = 0.f;
#pragma unroll
            for (int kk = 0; kk < 8; kk++) {
                unsigned bb[2];
                int base = (nt * 8 + g) * KS_PITCH + kk * 8 + tg;
                bb[0] = Ks[base]; bb[1] = Ks[base + 4];
                mma8(s[nt], qa[kk], bb);
            }
        }

        // Online softmax (per-row, 4-lane groups)
#pragma unroll
        for (int rr = 0; rr < 2; rr++) {
            float rm = -INFINITY;
#pragma unroll
            for (int nt = 0; nt < 8; nt++)
                rm = fmaxf(rm, fmaxf(s[nt][rr * 2], s[nt][rr * 2 + 1]));
            rm = fmaxf(rm, __shfl_xor_sync(0xffffffffu, rm, 1));
            rm = fmaxf(rm, __shfl_xor_sync(0xffffffffu, rm, 2));
            float mnew  = fmaxf(mx[rr], rm);
            float alpha = __expf(mx[rr] - mnew);
            mx[rr] = mnew;
            float rs = 0.f;
            int prow = (warp * 16 + g + rr * 8) * PS_PITCH;
#pragma unroll
            for (int nt = 0; nt < 8; nt++) {
                float p0 = __expf(s[nt][rr * 2]     - mnew);
                float p1 = __expf(s[nt][rr * 2 + 1] - mnew);
                rs += p0 + p1;
                uint2 pw = {f2t(p0), f2t(p1)};
                *(uint2*)&Ps[prow + nt * 8 + 2 * tg] = pw;
            }
            rs += __shfl_xor_sync(0xffffffffu, rs, 1);
            rs += __shfl_xor_sync(0xffffffffu, rs, 2);
            l[rr] = l[rr] * alpha + rs;
#pragma unroll
            for (int nt = 0; nt < 8; nt++) {
                o[nt][rr * 2]     *= alpha;
                o[nt][rr * 2 + 1] *= alpha;
            }
        }
        __syncthreads();

        // O += P @ V
#pragma unroll
        for (int kk = 0; kk < 8; kk++) {
            unsigned pa[4];
            int pr = (warp * 16 + g) * PS_PITCH + kk * 8 + tg;
            pa[0] = Ps[pr];
            pa[1] = Ps[pr + 8 * PS_PITCH];
            pa[2] = Ps[pr + 4];
            pa[3] = Ps[pr + 8 * PS_PITCH + 4];
#pragma unroll
            for (int nt = 0; nt < 8; nt++) {
                unsigned bb[2];
                int vb = (kk * 8 + tg) * VS_PITCH + nt * 8 + g;
                bb[0] = Vs[vb];
                bb[1] = Vs[vb + 4 * VS_PITCH];
                mma8(o[nt], pa, bb);
            }
        }
        __syncthreads();
    }

    // Epilogue: normalize and write to g_attn [B,S,D]
#pragma unroll
    for (int rr = 0; rr < 2; rr++) {
        float inv = 1.f / l[rr];
        int srow = qt * 128 + warp * 16 + g + rr * 8;
#pragma unroll
        for (int nt = 0; nt < 8; nt++) {
            float2 val = {o[nt][rr * 2] * inv, o[nt][rr * 2 + 1] * inv};
            *(float2*)&g_attn[((size_t)b * SS + srow) * DD + h * HD + nt * 8 + 2 * tg] = val;
        }
    }
}

// ---------------------------------------------------------------------------
extern "C" void kernel_launch(void* const* d_in, const int* in_sizes, int n_in,
                              void* d_out, int out_size)
{
    const float* x     = (const float*)d_in[0];   // [2,2048,1024]
    const float* w_qkv = (const float*)d_in[1];   // [3072,1024]
    const float* w_out = (const float*)d_in[2];   // [1024,1024]
    float* out = (float*)d_out;                   // [2,2048,1024]

    float* g_attn_ptr;
    cudaGetSymbolAddress((void**)&g_attn_ptr, g_attn);

    static bool attr_set = false;
    if (!attr_set) {
        cudaFuncSetAttribute(attn_tc, cudaFuncAttributeMaxDynamicSharedMemorySize,
                             SMEM_ATTN);
        attr_set = true;
    }

    // 1) QKV projection (tf32x3) + head scatter
    dim3 g1(3072 / 128, MM / 128);
    gemm_tc<0><<<g1, 256>>>(x, w_qkv, nullptr);

    // 2) Attention (tf32 flash)
    dim3 g2(SS / 128, HH, BB);
    attn_tc<<<g2, 256, SMEM_ATTN>>>();

    // 3) Output projection (tf32x3)
    dim3 g3(DD / 128, MM / 128);
    gemm_tc<1><<<g3, 256>>>(g_attn_ptr, w_out, out);
}

// round 6
// speedup vs baseline: 3.3385x; 1.6195x over previous
#include <cuda_runtime.h>
#include <math.h>

// Problem constants
#define BB 2
#define SS 2048
#define DD 1024
#define HH 16
#define HD 64
#define MM (BB * SS)   // 4096 rows

// Scratch (device globals: allocation-free per harness rules)
__device__ float g_q[BB * HH * SS * HD];     // [B,H,S,hd]
__device__ float g_k[BB * HH * SS * HD];
__device__ float g_v[BB * HH * SS * HD];
__device__ float g_attn[MM * DD];            // [B,S,D]

// ---------------------------------------------------------------------------
// tf32 helpers
// ---------------------------------------------------------------------------
__device__ __forceinline__ unsigned f2t(float x) {
    unsigned r;
    asm("cvt.rna.tf32.f32 %0, %1;" : "=r"(r) : "f"(x));
    return r;
}

__device__ __forceinline__ void mma8(float c[4], const unsigned a[4],
                                     const unsigned b[2]) {
    asm volatile(
        "mma.sync.aligned.m16n8k8.row.col.f32.tf32.tf32.f32 "
        "{%0,%1,%2,%3}, {%4,%5,%6,%7}, {%8,%9}, {%0,%1,%2,%3};"
        : "+f"(c[0]), "+f"(c[1]), "+f"(c[2]), "+f"(c[3])
        : "r"(a[0]), "r"(a[1]), "r"(a[2]), "r"(a[3]), "r"(b[0]), "r"(b[1]));
}

// ---------------------------------------------------------------------------
// Plain-tf32 NT GEMM: C[M,N] = A[M,K] @ W[N,K]^T, K=1024. BM=BN=128, BK=16,
// double-buffered smem (40KB). 8 warps: 2(m) x 4(n), warp tile 64x32.
// MODE 0: scatter epilogue into g_q/g_k/g_v.   MODE 1: row-major into out.
// ---------------------------------------------------------------------------
template <int MODE>
__global__ void __launch_bounds__(256, 2) gemm_tc(
    const float* __restrict__ A, const float* __restrict__ W,
    float* __restrict__ out)
{
    constexpr int K = 1024, BK = 16, PITCH = 20;
    __shared__ unsigned As[2][128 * PITCH];
    __shared__ unsigned Bs[2][128 * PITCH];

    const int tid  = threadIdx.x;
    const int lane = tid & 31, warp = tid >> 5;
    const int wm = warp >> 2, wn = warp & 3;   // 2 x 4 warp grid
    const int m0 = blockIdx.y * 128, n0 = blockIdx.x * 128;
    const int g = lane >> 2, tg = lane & 3;

    const int lrow = tid >> 2;          // 0..63
    const int lc4  = (tid & 3) * 4;     // 0,4,8,12
    const float* Aptr = A + (size_t)(m0 + lrow) * K + lc4;
    const float* Wptr = W + (size_t)(n0 + lrow) * K + lc4;

    float acc[4][4][4];
#pragma unroll
    for (int i = 0; i < 4; i++)
#pragma unroll
        for (int j = 0; j < 4; j++)
#pragma unroll
            for (int c = 0; c < 4; c++) acc[i][j][c] = 0.f;

    auto stage = [&](int buf, float4 a0, float4 a1, float4 w0, float4 w1) {
        *(uint4*)&As[buf][lrow * PITCH + lc4] =
            make_uint4(f2t(a0.x), f2t(a0.y), f2t(a0.z), f2t(a0.w));
        *(uint4*)&As[buf][(lrow + 64) * PITCH + lc4] =
            make_uint4(f2t(a1.x), f2t(a1.y), f2t(a1.z), f2t(a1.w));
        *(uint4*)&Bs[buf][lrow * PITCH + lc4] =
            make_uint4(f2t(w0.x), f2t(w0.y), f2t(w0.z), f2t(w0.w));
        *(uint4*)&Bs[buf][(lrow + 64) * PITCH + lc4] =
            make_uint4(f2t(w1.x), f2t(w1.y), f2t(w1.z), f2t(w1.w));
    };

    auto compute = [&](int buf) {
#pragma unroll
        for (int kk = 0; kk < 2; kk++) {
            unsigned bf[4][2];
#pragma unroll
            for (int nt = 0; nt < 4; nt++) {
                int r = (wn * 32 + nt * 8 + g) * PITCH + kk * 8 + tg;
                bf[nt][0] = Bs[buf][r]; bf[nt][1] = Bs[buf][r + 4];
            }
#pragma unroll
            for (int mt = 0; mt < 4; mt++) {
                int r0 = (wm * 64 + mt * 16 + g) * PITCH + kk * 8 + tg;
                int r1 = r0 + 8 * PITCH;
                unsigned af[4] = {As[buf][r0], As[buf][r1],
                                  As[buf][r0 + 4], As[buf][r1 + 4]};
#pragma unroll
                for (int nt = 0; nt < 4; nt++)
                    mma8(acc[mt][nt], af, bf[nt]);
            }
        }
    };

    {
        float4 a0 = *(const float4*)Aptr;
        float4 a1 = *(const float4*)(Aptr + (size_t)64 * K);
        float4 w0 = *(const float4*)Wptr;
        float4 w1 = *(const float4*)(Wptr + (size_t)64 * K);
        stage(0, a0, a1, w0, w1);
    }
    __syncthreads();
    int buf = 0;
    for (int k0 = BK; k0 < K; k0 += BK) {
        float4 a0 = *(const float4*)(Aptr + k0);
        float4 a1 = *(const float4*)(Aptr + (size_t)64 * K + k0);
        float4 w0 = *(const float4*)(Wptr + k0);
        float4 w1 = *(const float4*)(Wptr + (size_t)64 * K + k0);
        compute(buf);
        stage(buf ^ 1, a0, a1, w0, w1);
        __syncthreads();
        buf ^= 1;
    }
    compute(buf);

    // Epilogue
    if (MODE == 0) {
#pragma unroll
        for (int mt = 0; mt < 4; mt++) {
#pragma unroll
            for (int rr = 0; rr < 2; rr++) {
                int m = m0 + wm * 64 + mt * 16 + g + rr * 8;
                int b = m >> 11, s = m & 2047;
#pragma unroll
                for (int nt = 0; nt < 4; nt++) {
                    int n = n0 + wn * 32 + nt * 8 + 2 * tg;
                    int which = n >> 10;
                    int rem = n & 1023, h = rem >> 6, d = rem & 63;
                    float* dst = (which == 0) ? g_q : (which == 1) ? g_k : g_v;
                    float2 val = {acc[mt][nt][rr * 2], acc[mt][nt][rr * 2 + 1]};
                    *(float2*)&dst[(((size_t)b * HH + h) * SS + s) * HD + d] = val;
                }
            }
        }
    } else {
#pragma unroll
        for (int mt = 0; mt < 4; mt++) {
#pragma unroll
            for (int rr = 0; rr < 2; rr++) {
                int m = m0 + wm * 64 + mt * 16 + g + rr * 8;
#pragma unroll
                for (int nt = 0; nt < 4; nt++) {
                    int n = n0 + wn * 32 + nt * 8 + 2 * tg;
                    float2 val = {acc[mt][nt][rr * 2], acc[mt][nt][rr * 2 + 1]};
                    *(float2*)&out[(size_t)m * DD + n] = val;
                }
            }
        }
    }
}

// ---------------------------------------------------------------------------
// tf32 flash attention v2: 128 threads = 4 warps x 32 q-rows (BQ=128),
// 64-key blocks. P kept in registers: C-layout -> A-layout via warp shfl
// (no P smem, no extra barrier). Static smem 35840 B -> 2 CTAs/SM.
// ---------------------------------------------------------------------------
#define KS_PITCH 68
#define VS_PITCH 72

__global__ void __launch_bounds__(128) attn_tc()
{
    __shared__ unsigned Ks[64 * KS_PITCH];
    __shared__ unsigned Vs[64 * VS_PITCH];

    const int qt = blockIdx.x, h = blockIdx.y, b = blockIdx.z;
    const int tid = threadIdx.x, lane = tid & 31, warp = tid >> 5;
    const int g = lane >> 2, tg = lane & 3;
    const int idx0 = (lane & 28) | (tg >> 1);

    const size_t hb = ((size_t)b * HH + h) * SS * HD;
    const float* qp = g_q + hb + (size_t)(qt * 128 + warp * 32) * HD;
    const float* kp = g_k + hb;
    const float* vp = g_v + hb;

    // Q fragments in registers (2 m-tiles of 16 rows), pre-scaled by 0.125
    unsigned qa[2][8][4];
#pragma unroll
    for (int mt = 0; mt < 2; mt++) {
        int r0 = mt * 16 + g, r1 = r0 + 8;
#pragma unroll
        for (int kk = 0; kk < 8; kk++) {
            int c0 = kk * 8 + tg, c1 = c0 + 4;
            qa[mt][kk][0] = f2t(0.125f * qp[(size_t)r0 * HD + c0]);
            qa[mt][kk][1] = f2t(0.125f * qp[(size_t)r1 * HD + c0]);
            qa[mt][kk][2] = f2t(0.125f * qp[(size_t)r0 * HD + c1]);
            qa[mt][kk][3] = f2t(0.125f * qp[(size_t)r1 * HD + c1]);
        }
    }

    float o[2][8][4];
#pragma unroll
    for (int mt = 0; mt < 2; mt++)
#pragma unroll
        for (int nt = 0; nt < 8; nt++)
#pragma unroll
            for (int c = 0; c < 4; c++) o[mt][nt][c] = 0.f;
    float mx[2][2] = {{-INFINITY, -INFINITY}, {-INFINITY, -INFINITY}};
    float l[2][2] = {{0.f, 0.f}, {0.f, 0.f}};

    for (int kb = 0; kb < SS / 64; kb++) {
        __syncthreads();   // previous iteration's smem readers done
        // Load K,V 64x64 tiles (cvt to tf32); 128 threads x 8 float4 each
#pragma unroll
        for (int p = 0; p < 8; p++) {
            int v = tid + p * 128;             // 0..1023
            int row = v >> 4, c4 = (v & 15) * 4;
            float4 kv = *(const float4*)&kp[((size_t)kb * 64 + row) * HD + c4];
            *(uint4*)&Ks[row * KS_PITCH + c4] =
                make_uint4(f2t(kv.x), f2t(kv.y), f2t(kv.z), f2t(kv.w));
            float4 vv = *(const float4*)&vp[((size_t)kb * 64 + row) * HD + c4];
            *(uint4*)&Vs[row * VS_PITCH + c4] =
                make_uint4(f2t(vv.x), f2t(vv.y), f2t(vv.z), f2t(vv.w));
        }
        __syncthreads();

        // S = Q @ K^T : per warp 32 rows x 64 keys
        float s[2][8][4];
#pragma unroll
        for (int mt = 0; mt < 2; mt++)
#pragma unroll
            for (int nt = 0; nt < 8; nt++)
#pragma unroll
                for (int c = 0; c < 4; c++) s[mt][nt][c] = 0.f;
#pragma unroll
        for (int kk = 0; kk < 8; kk++) {
#pragma unroll
            for (int nt = 0; nt < 8; nt++) {
                unsigned kf[2];
                int base = (nt * 8 + g) * KS_PITCH + kk * 8 + tg;
                kf[0] = Ks[base]; kf[1] = Ks[base + 4];
                mma8(s[0][nt], qa[0][kk], kf);
                mma8(s[1][nt], qa[1][kk], kf);
            }
        }

        // Online softmax; p overwrites s in place
#pragma unroll
        for (int mt = 0; mt < 2; mt++) {
#pragma unroll
            for (int rr = 0; rr < 2; rr++) {
                float rm = -INFINITY;
#pragma unroll
                for (int nt = 0; nt < 8; nt++)
                    rm = fmaxf(rm, fmaxf(s[mt][nt][rr * 2], s[mt][nt][rr * 2 + 1]));
                rm = fmaxf(rm, __shfl_xor_sync(0xffffffffu, rm, 1));
                rm = fmaxf(rm, __shfl_xor_sync(0xffffffffu, rm, 2));
                float mnew  = fmaxf(mx[mt][rr], rm);
                float alpha = __expf(mx[mt][rr] - mnew);
                mx[mt][rr] = mnew;
                float rs = 0.f;
#pragma unroll
                for (int nt = 0; nt < 8; nt++) {
                    float p0 = __expf(s[mt][nt][rr * 2]     - mnew);
                    float p1 = __expf(s[mt][nt][rr * 2 + 1] - mnew);
                    s[mt][nt][rr * 2]     = p0;
                    s[mt][nt][rr * 2 + 1] = p1;
                    rs += p0 + p1;
                }
                rs += __shfl_xor_sync(0xffffffffu, rs, 1);
                rs += __shfl_xor_sync(0xffffffffu, rs, 2);
                l[mt][rr] = l[mt][rr] * alpha + rs;
#pragma unroll
                for (int nt = 0; nt < 8; nt++) {
                    o[mt][nt][rr * 2]     *= alpha;
                    o[mt][nt][rr * 2 + 1] *= alpha;
                }
            }
        }

        // O += P @ V; P converted C-layout -> A-layout via shfl (no smem)
#pragma unroll
        for (int kk = 0; kk < 8; kk++) {
            unsigned pa[2][4];
#pragma unroll
            for (int mt = 0; mt < 2; mt++) {
                unsigned p0 = f2t(s[mt][kk][0]), p1 = f2t(s[mt][kk][1]);
                unsigned p2 = f2t(s[mt][kk][2]), p3 = f2t(s[mt][kk][3]);
                unsigned x, y;
                x = __shfl_sync(0xffffffffu, p0, idx0);
                y = __shfl_sync(0xffffffffu, p1, idx0);
                pa[mt][0] = (tg & 1) ? y : x;
                x = __shfl_sync(0xffffffffu, p2, idx0);
                y = __shfl_sync(0xffffffffu, p3, idx0);
                pa[mt][1] = (tg & 1) ? y : x;
                x = __shfl_sync(0xffffffffu, p0, idx0 + 2);
                y = __shfl_sync(0xffffffffu, p1, idx0 + 2);
                pa[mt][2] = (tg & 1) ? y : x;
                x = __shfl_sync(0xffffffffu, p2, idx0 + 2);
                y = __shfl_sync(0xffffffffu, p3, idx0 + 2);
                pa[mt][3] = (tg & 1) ? y : x;
            }
#pragma unroll
            for (int nt = 0; nt < 8; nt++) {
                unsigned vf[2];
                int vb = (kk * 8 + tg) * VS_PITCH + nt * 8 + g;
                vf[0] = Vs[vb]; vf[1] = Vs[vb + 4 * VS_PITCH];
                mma8(o[0][nt], pa[0], vf);
                mma8(o[1][nt], pa[1], vf);
            }
        }
    }

    // Epilogue: normalize and write to g_attn [B,S,D]
#pragma unroll
    for (int mt = 0; mt < 2; mt++) {
#pragma unroll
        for (int rr = 0; rr < 2; rr++) {
            float inv = 1.f / l[mt][rr];
            int srow = qt * 128 + warp * 32 + mt * 16 + g + rr * 8;
#pragma unroll
            for (int nt = 0; nt < 8; nt++) {
                float2 val = {o[mt][nt][rr * 2] * inv, o[mt][nt][rr * 2 + 1] * inv};
                *(float2*)&g_attn[((size_t)b * SS + srow) * DD + h * HD +
                                  nt * 8 + 2 * tg] = val;
            }
        }
    }
}

// ---------------------------------------------------------------------------
extern "C" void kernel_launch(void* const* d_in, const int* in_sizes, int n_in,
                              void* d_out, int out_size)
{
    const float* x     = (const float*)d_in[0];   // [2,2048,1024]
    const float* w_qkv = (const float*)d_in[1];   // [3072,1024]
    const float* w_out = (const float*)d_in[2];   // [1024,1024]
    float* out = (float*)d_out;                   // [2,2048,1024]

    float* g_attn_ptr;
    cudaGetSymbolAddress((void**)&g_attn_ptr, g_attn);

    // 1) QKV projection (tf32) + head scatter
    dim3 g1(3072 / 128, MM / 128);
    gemm_tc<0><<<g1, 256>>>(x, w_qkv, nullptr);

    // 2) Attention (tf32 flash, register-resident P)
    dim3 g2(SS / 128, HH, BB);
    attn_tc<<<g2, 128>>>();

    // 3) Output projection (tf32)
    dim3 g3(DD / 128, MM / 128);
    gemm_tc<1><<<g3, 256>>>(g_attn_ptr, w_out, out);
}

// round 10
// speedup vs baseline: 3.3449x; 1.0019x over previous
#include <cuda_runtime.h>
#include <math.h>

// Problem constants
#define BB 2
#define SS 2048
#define DD 1024
#define HH 16
#define HD 64
#define MM (BB * SS)   // 4096 rows

// Scratch (device globals: allocation-free per harness rules)
__device__ float g_q[BB * HH * SS * HD];     // [B,H,S,hd]
__device__ float g_k[BB * HH * SS * HD];
__device__ float g_v[BB * HH * SS * HD];
__device__ float g_attn[MM * DD];            // [B,S,D]

// ---------------------------------------------------------------------------
// tf32 helpers
// ---------------------------------------------------------------------------
__device__ __forceinline__ unsigned f2t(float x) {
    unsigned r;
    asm("cvt.rna.tf32.f32 %0, %1;" : "=r"(r) : "f"(x));
    return r;
}

__device__ __forceinline__ void mma8(float c[4], const unsigned a[4],
                                     const unsigned b[2]) {
    asm volatile(
        "mma.sync.aligned.m16n8k8.row.col.f32.tf32.tf32.f32 "
        "{%0,%1,%2,%3}, {%4,%5,%6,%7}, {%8,%9}, {%0,%1,%2,%3};"
        : "+f"(c[0]), "+f"(c[1]), "+f"(c[2]), "+f"(c[3])
        : "r"(a[0]), "r"(a[1]), "r"(a[2]), "r"(a[3]), "r"(b[0]), "r"(b[1]));
}

// ---------------------------------------------------------------------------
// Plain-tf32 NT GEMM: C[M,N] = A[M,K] @ W[N,K]^T, K=1024. BM=BN=128, BK=16,
// double-buffered smem (40KB). 8 warps: 2(m) x 4(n), warp tile 64x32.
// MODE 0: scatter epilogue into g_q/g_k/g_v.   MODE 1: row-major into out.
// ---------------------------------------------------------------------------
template <int MODE>
__global__ void __launch_bounds__(256, 2) gemm_tc(
    const float* __restrict__ A, const float* __restrict__ W,
    float* __restrict__ out)
{
    constexpr int K = 1024, BK = 16, PITCH = 20;
    __shared__ unsigned As[2][128 * PITCH];
    __shared__ unsigned Bs[2][128 * PITCH];

    const int tid  = threadIdx.x;
    const int lane = tid & 31, warp = tid >> 5;
    const int wm = warp >> 2, wn = warp & 3;   // 2 x 4 warp grid
    const int m0 = blockIdx.y * 128, n0 = blockIdx.x * 128;
    const int g = lane >> 2, tg = lane & 3;

    const int lrow = tid >> 2;          // 0..63
    const int lc4  = (tid & 3) * 4;     // 0,4,8,12
    const float* Aptr = A + (size_t)(m0 + lrow) * K + lc4;
    const float* Wptr = W + (size_t)(n0 + lrow) * K + lc4;

    float acc[4][4][4];
#pragma unroll
    for (int i = 0; i < 4; i++)
#pragma unroll
        for (int j = 0; j < 4; j++)
#pragma unroll
            for (int c = 0; c < 4; c++) acc[i][j][c] = 0.f;

    auto stage = [&](int buf, float4 a0, float4 a1, float4 w0, float4 w1) {
        *(uint4*)&As[buf][lrow * PITCH + lc4] =
            make_uint4(f2t(a0.x), f2t(a0.y), f2t(a0.z), f2t(a0.w));
        *(uint4*)&As[buf][(lrow + 64) * PITCH + lc4] =
            make_uint4(f2t(a1.x), f2t(a1.y), f2t(a1.z), f2t(a1.w));
        *(uint4*)&Bs[buf][lrow * PITCH + lc4] =
            make_uint4(f2t(w0.x), f2t(w0.y), f2t(w0.z), f2t(w0.w));
        *(uint4*)&Bs[buf][(lrow + 64) * PITCH + lc4] =
            make_uint4(f2t(w1.x), f2t(w1.y), f2t(w1.z), f2t(w1.w));
    };

    auto compute = [&](int buf) {
#pragma unroll
        for (int kk = 0; kk < 2; kk++) {
            unsigned bf[4][2];
#pragma unroll
            for (int nt = 0; nt < 4; nt++) {
                int r = (wn * 32 + nt * 8 + g) * PITCH + kk * 8 + tg;
                bf[nt][0] = Bs[buf][r]; bf[nt][1] = Bs[buf][r + 4];
            }
#pragma unroll
            for (int mt = 0; mt < 4; mt++) {
                int r0 = (wm * 64 + mt * 16 + g) * PITCH + kk * 8 + tg;
                int r1 = r0 + 8 * PITCH;
                unsigned af[4] = {As[buf][r0], As[buf][r1],
                                  As[buf][r0 + 4], As[buf][r1 + 4]};
#pragma unroll
                for (int nt = 0; nt < 4; nt++)
                    mma8(acc[mt][nt], af, bf[nt]);
            }
        }
    };

    {
        float4 a0 = *(const float4*)Aptr;
        float4 a1 = *(const float4*)(Aptr + (size_t)64 * K);
        float4 w0 = *(const float4*)Wptr;
        float4 w1 = *(const float4*)(Wptr + (size_t)64 * K);
        stage(0, a0, a1, w0, w1);
    }
    __syncthreads();
    int buf = 0;
    for (int k0 = BK; k0 < K; k0 += BK) {
        float4 a0 = *(const float4*)(Aptr + k0);
        float4 a1 = *(const float4*)(Aptr + (size_t)64 * K + k0);
        float4 w0 = *(const float4*)(Wptr + k0);
        float4 w1 = *(const float4*)(Wptr + (size_t)64 * K + k0);
        compute(buf);
        stage(buf ^ 1, a0, a1, w0, w1);
        __syncthreads();
        buf ^= 1;
    }
    compute(buf);

    // Epilogue
    if (MODE == 0) {
#pragma unroll
        for (int mt = 0; mt < 4; mt++) {
#pragma unroll
            for (int rr = 0; rr < 2; rr++) {
                int m = m0 + wm * 64 + mt * 16 + g + rr * 8;
                int b = m >> 11, s = m & 2047;
#pragma unroll
                for (int nt = 0; nt < 4; nt++) {
                    int n = n0 + wn * 32 + nt * 8 + 2 * tg;
                    int which = n >> 10;
                    int rem = n & 1023, h = rem >> 6, d = rem & 63;
                    float* dst = (which == 0) ? g_q : (which == 1) ? g_k : g_v;
                    float2 val = {acc[mt][nt][rr * 2], acc[mt][nt][rr * 2 + 1]};
                    *(float2*)&dst[(((size_t)b * HH + h) * SS + s) * HD + d] = val;
                }
            }
        }
    } else {
#pragma unroll
        for (int mt = 0; mt < 4; mt++) {
#pragma unroll
            for (int rr = 0; rr < 2; rr++) {
                int m = m0 + wm * 64 + mt * 16 + g + rr * 8;
#pragma unroll
                for (int nt = 0; nt < 4; nt++) {
                    int n = n0 + wn * 32 + nt * 8 + 2 * tg;
                    float2 val = {acc[mt][nt][rr * 2], acc[mt][nt][rr * 2 + 1]};
                    *(float2*)&out[(size_t)m * DD + n] = val;
                }
            }
        }
    }
}

// ---------------------------------------------------------------------------
// tf32 flash attention v2: 128 threads = 4 warps x 32 q-rows (BQ=128),
// 64-key blocks. P kept in registers: C-layout -> A-layout via warp shfl
// (no P smem, no extra barrier). Static smem 35840 B -> 2 CTAs/SM.
// ---------------------------------------------------------------------------
#define KS_PITCH 68
#define VS_PITCH 72

__global__ void __launch_bounds__(128) attn_tc()
{
    __shared__ unsigned Ks[64 * KS_PITCH];
    __shared__ unsigned Vs[64 * VS_PITCH];

    const int qt = blockIdx.x, h = blockIdx.y, b = blockIdx.z;
    const int tid = threadIdx.x, lane = tid & 31, warp = tid >> 5;
    const int g = lane >> 2, tg = lane & 3;
    const int idx0 = (lane & 28) | (tg >> 1);

    const size_t hb = ((size_t)b * HH + h) * SS * HD;
    const float* qp = g_q + hb + (size_t)(qt * 128 + warp * 32) * HD;
    const float* kp = g_k + hb;
    const float* vp = g_v + hb;

    // Q fragments in registers (2 m-tiles of 16 rows), pre-scaled by 0.125
    unsigned qa[2][8][4];
#pragma unroll
    for (int mt = 0; mt < 2; mt++) {
        int r0 = mt * 16 + g, r1 = r0 + 8;
#pragma unroll
        for (int kk = 0; kk < 8; kk++) {
            int c0 = kk * 8 + tg, c1 = c0 + 4;
            qa[mt][kk][0] = f2t(0.125f * qp[(size_t)r0 * HD + c0]);
            qa[mt][kk][1] = f2t(0.125f * qp[(size_t)r1 * HD + c0]);
            qa[mt][kk][2] = f2t(0.125f * qp[(size_t)r0 * HD + c1]);
            qa[mt][kk][3] = f2t(0.125f * qp[(size_t)r1 * HD + c1]);
        }
    }

    float o[2][8][4];
#pragma unroll
    for (int mt = 0; mt < 2; mt++)
#pragma unroll
        for (int nt = 0; nt < 8; nt++)
#pragma unroll
            for (int c = 0; c < 4; c++) o[mt][nt][c] = 0.f;
    float mx[2][2] = {{-INFINITY, -INFINITY}, {-INFINITY, -INFINITY}};
    float l[2][2] = {{0.f, 0.f}, {0.f, 0.f}};

    for (int kb = 0; kb < SS / 64; kb++) {
        __syncthreads();   // previous iteration's smem readers done
        // Load K,V 64x64 tiles (cvt to tf32); 128 threads x 8 float4 each
#pragma unroll
        for (int p = 0; p < 8; p++) {
            int v = tid + p * 128;             // 0..1023
            int row = v >> 4, c4 = (v & 15) * 4;
            float4 kv = *(const float4*)&kp[((size_t)kb * 64 + row) * HD + c4];
            *(uint4*)&Ks[row * KS_PITCH + c4] =
                make_uint4(f2t(kv.x), f2t(kv.y), f2t(kv.z), f2t(kv.w));
            float4 vv = *(const float4*)&vp[((size_t)kb * 64 + row) * HD + c4];
            *(uint4*)&Vs[row * VS_PITCH + c4] =
                make_uint4(f2t(vv.x), f2t(vv.y), f2t(vv.z), f2t(vv.w));
        }
        __syncthreads();

        // S = Q @ K^T : per warp 32 rows x 64 keys
        float s[2][8][4];
#pragma unroll
        for (int mt = 0; mt < 2; mt++)
#pragma unroll
            for (int nt = 0; nt < 8; nt++)
#pragma unroll
                for (int c = 0; c < 4; c++) s[mt][nt][c] = 0.f;
#pragma unroll
        for (int kk = 0; kk < 8; kk++) {
#pragma unroll
            for (int nt = 0; nt < 8; nt++) {
                unsigned kf[2];
                int base = (nt * 8 + g) * KS_PITCH + kk * 8 + tg;
                kf[0] = Ks[base]; kf[1] = Ks[base + 4];
                mma8(s[0][nt], qa[0][kk], kf);
                mma8(s[1][nt], qa[1][kk], kf);
            }
        }

        // Online softmax; p overwrites s in place
#pragma unroll
        for (int mt = 0; mt < 2; mt++) {
#pragma unroll
            for (int rr = 0; rr < 2; rr++) {
                float rm = -INFINITY;
#pragma unroll
                for (int nt = 0; nt < 8; nt++)
                    rm = fmaxf(rm, fmaxf(s[mt][nt][rr * 2], s[mt][nt][rr * 2 + 1]));
                rm = fmaxf(rm, __shfl_xor_sync(0xffffffffu, rm, 1));
                rm = fmaxf(rm, __shfl_xor_sync(0xffffffffu, rm, 2));
                float mnew  = fmaxf(mx[mt][rr], rm);
                float alpha = __expf(mx[mt][rr] - mnew);
                mx[mt][rr] = mnew;
                float rs = 0.f;
#pragma unroll
                for (int nt = 0; nt < 8; nt++) {
                    float p0 = __expf(s[mt][nt][rr * 2]     - mnew);
                    float p1 = __expf(s[mt][nt][rr * 2 + 1] - mnew);
                    s[mt][nt][rr * 2]     = p0;
                    s[mt][nt][rr * 2 + 1] = p1;
                    rs += p0 + p1;
                }
                rs += __shfl_xor_sync(0xffffffffu, rs, 1);
                rs += __shfl_xor_sync(0xffffffffu, rs, 2);
                l[mt][rr] = l[mt][rr] * alpha + rs;
#pragma unroll
                for (int nt = 0; nt < 8; nt++) {
                    o[mt][nt][rr * 2]     *= alpha;
                    o[mt][nt][rr * 2 + 1] *= alpha;
                }
            }
        }

        // O += P @ V; P converted C-layout -> A-layout via shfl (no smem)
#pragma unroll
        for (int kk = 0; kk < 8; kk++) {
            unsigned pa[2][4];
#pragma unroll
            for (int mt = 0; mt < 2; mt++) {
                unsigned p0 = f2t(s[mt][kk][0]), p1 = f2t(s[mt][kk][1]);
                unsigned p2 = f2t(s[mt][kk][2]), p3 = f2t(s[mt][kk][3]);
                unsigned x, y;
                x = __shfl_sync(0xffffffffu, p0, idx0);
                y = __shfl_sync(0xffffffffu, p1, idx0);
                pa[mt][0] = (tg & 1) ? y : x;
                x = __shfl_sync(0xffffffffu, p2, idx0);
                y = __shfl_sync(0xffffffffu, p3, idx0);
                pa[mt][1] = (tg & 1) ? y : x;
                x = __shfl_sync(0xffffffffu, p0, idx0 + 2);
                y = __shfl_sync(0xffffffffu, p1, idx0 + 2);
                pa[mt][2] = (tg & 1) ? y : x;
                x = __shfl_sync(0xffffffffu, p2, idx0 + 2);
                y = __shfl_sync(0xffffffffu, p3, idx0 + 2);
                pa[mt][3] = (tg & 1) ? y : x;
            }
#pragma unroll
            for (int nt = 0; nt < 8; nt++) {
                unsigned vf[2];
                int vb = (kk * 8 + tg) * VS_PITCH + nt * 8 + g;
                vf[0] = Vs[vb]; vf[1] = Vs[vb + 4 * VS_PITCH];
                mma8(o[0][nt], pa[0], vf);
                mma8(o[1][nt], pa[1], vf);
            }
        }
    }

    // Epilogue: normalize and write to g_attn [B,S,D]
#pragma unroll
    for (int mt = 0; mt < 2; mt++) {
#pragma unroll
        for (int rr = 0; rr < 2; rr++) {
            float inv = 1.f / l[mt][rr];
            int srow = qt * 128 + warp * 32 + mt * 16 + g + rr * 8;
#pragma unroll
            for (int nt = 0; nt < 8; nt++) {
                float2 val = {o[mt][nt][rr * 2] * inv, o[mt][nt][rr * 2 + 1] * inv};
                *(float2*)&g_attn[((size_t)b * SS + srow) * DD + h * HD +
                                  nt * 8 + 2 * tg] = val;
            }
        }
    }
}

// ---------------------------------------------------------------------------
extern "C" void kernel_launch(void* const* d_in, const int* in_sizes, int n_in,
                              void* d_out, int out_size)
{
    const float* x     = (const float*)d_in[0];   // [2,2048,1024]
    const float* w_qkv = (const float*)d_in[1];   // [3072,1024]
    const float* w_out = (const float*)d_in[2];   // [1024,1024]
    float* out = (float*)d_out;                   // [2,2048,1024]

    float* g_attn_ptr;
    cudaGetSymbolAddress((void**)&g_attn_ptr, g_attn);

    // 1) QKV projection (tf32) + head scatter
    dim3 g1(3072 / 128, MM / 128);
    gemm_tc<0><<<g1, 256>>>(x, w_qkv, nullptr);

    // 2) Attention (tf32 flash, register-resident P)
    dim3 g2(SS / 128, HH, BB);
    attn_tc<<<g2, 128>>>();

    // 3) Output projection (tf32)
    dim3 g3(DD / 128, MM / 128);
    gemm_tc<1><<<g3, 256>>>(g_attn_ptr, w_out, out);
}